// round 5
// baseline (speedup 1.0000x reference)
#include <cuda_runtime.h>

// ---------------------------------------------------------------------------
// TNModel binary-tree TN, B=65536. Round 5: eighth-tree split.
// Kernel 1: each CTA computes one eighth subtree (levels w7..w3, 19 KB
// weights in smem) for 2 samples/thread, 128-thread CTAs, 5 CTAs/SM
// (launch_bounds cap 102 regs; natural ~110 -> tiny cold spill) -> 20 warps/SM.
// Kernel 2: merges 8 eighth-vectors via w2 (4x) + w1 (2x) + w0 root, SPT=2.
// ---------------------------------------------------------------------------

#define NB       65536
#define HALF     (NB / 2)            // 32768
#define T1       128                 // threads, kernel 1
#define BLK_E    (HALF / T1)         // 256 blocks per eighth
#define NBLOCKS1 (8 * BLK_E)         // 2048
#define T2       128                 // threads, kernel 2
#define NBLOCKS2 (HALF / T2)         // 256 (SPT=2)

// eighth-tree shared-memory float offsets
#define E7 0                      // 16 x 16   =  256
#define E6 (E7 + 256)             //  8 x 128  = 1024
#define E5 (E6 + 1024)            //  4 x 512  = 2048
#define E4 (E5 + 2048)            //  2 x 512  = 1024
#define E3 (E4 + 1024)            //  1 x 512  =  512
#define SMEM1_FLOATS (E3 + 512)   // 4864 floats = 19456 bytes

typedef unsigned long long ull;

__device__ float4 g_ebuf[8 * NB * 2];   // [eighth][sample][2 x float4]

__device__ __forceinline__ ull ffma2(ull a, ull b, ull c) {
    ull d;
    asm("fma.rn.f32x2 %0, %1, %2, %3;" : "=l"(d) : "l"(a), "l"(b), "l"(c));
    return d;
}
__device__ __forceinline__ ull bcast2(float x) {
    ull r;
    asm("mov.b64 %0, {%1, %1};" : "=l"(r) : "f"(x));
    return r;
}
__device__ __forceinline__ void unpack2(ull v, float& lo, float& hi) {
    asm("mov.b64 {%0, %1}, %2;" : "=f"(lo), "=f"(hi) : "l"(v));
}
__device__ __forceinline__ void cp8(float* d, const float* s) {
#pragma unroll
    for (int k = 0; k < 8; ++k) d[k] = s[k];
}

// leaf for two samples sharing W (16 floats): h[k<4] = sum_{i,j<2} e_i o_j w[ijk]
__device__ __forceinline__ void leaf2(float4 qa, float4 qb,
                                      const float* __restrict__ w,
                                      float* hA, float* hB) {
    ull cA0 = 0, cA1 = 0, cB0 = 0, cB1 = 0;
    float eA[2] = {qa.x, qa.y}, oA[2] = {qa.z, qa.w};
    float eB[2] = {qb.x, qb.y}, oB[2] = {qb.z, qb.w};
#pragma unroll
    for (int i = 0; i < 2; ++i) {
#pragma unroll
        for (int j = 0; j < 2; ++j) {
            const ulonglong2 W = *reinterpret_cast<const ulonglong2*>(w + (i * 2 + j) * 4);
            ull pA = bcast2(eA[i] * oA[j]);
            ull pB = bcast2(eB[i] * oB[j]);
            cA0 = ffma2(pA, W.x, cA0);  cA1 = ffma2(pA, W.y, cA1);
            cB0 = ffma2(pB, W.x, cB0);  cB1 = ffma2(pB, W.y, cB1);
        }
    }
    unpack2(cA0, hA[0], hA[1]);  unpack2(cA1, hA[2], hA[3]);
    unpack2(cB0, hB[0], hB[1]);  unpack2(cB1, hB[2], hB[3]);
}

// 4x4->8, two samples sharing W (128 floats)
__device__ __forceinline__ void contract448_2(const float* aA, const float* bA,
                                              const float* aB, const float* bB,
                                              const float* __restrict__ w,
                                              float* outA, float* outB) {
    ull cA[4] = {0, 0, 0, 0}, cB[4] = {0, 0, 0, 0};
#pragma unroll
    for (int i = 0; i < 4; ++i) {
        ull tA[4] = {0, 0, 0, 0}, tB[4] = {0, 0, 0, 0};
#pragma unroll
        for (int j = 0; j < 4; ++j) {
            const ulonglong2* wp = reinterpret_cast<const ulonglong2*>(w + (i * 4 + j) * 8);
            ulonglong2 W01 = wp[0];
            ulonglong2 W23 = wp[1];
            ull bb = bcast2(bA[j]);
            tA[0] = ffma2(bb, W01.x, tA[0]);  tA[1] = ffma2(bb, W01.y, tA[1]);
            tA[2] = ffma2(bb, W23.x, tA[2]);  tA[3] = ffma2(bb, W23.y, tA[3]);
            bb = bcast2(bB[j]);
            tB[0] = ffma2(bb, W01.x, tB[0]);  tB[1] = ffma2(bb, W01.y, tB[1]);
            tB[2] = ffma2(bb, W23.x, tB[2]);  tB[3] = ffma2(bb, W23.y, tB[3]);
        }
        ull ai = bcast2(aA[i]);
        cA[0] = ffma2(ai, tA[0], cA[0]);  cA[1] = ffma2(ai, tA[1], cA[1]);
        cA[2] = ffma2(ai, tA[2], cA[2]);  cA[3] = ffma2(ai, tA[3], cA[3]);
        ai = bcast2(aB[i]);
        cB[0] = ffma2(ai, tB[0], cB[0]);  cB[1] = ffma2(ai, tB[1], cB[1]);
        cB[2] = ffma2(ai, tB[2], cB[2]);  cB[3] = ffma2(ai, tB[3], cB[3]);
    }
    unpack2(cA[0], outA[0], outA[1]);  unpack2(cA[1], outA[2], outA[3]);
    unpack2(cA[2], outA[4], outA[5]);  unpack2(cA[3], outA[6], outA[7]);
    unpack2(cB[0], outB[0], outB[1]);  unpack2(cB[1], outB[2], outB[3]);
    unpack2(cB[2], outB[4], outB[5]);  unpack2(cB[3], outB[6], outB[7]);
}

// 8x8->8, two samples sharing W (512 floats). out may alias b.
__device__ __forceinline__ void contract888_2(const float* aA, const float* bA,
                                              const float* aB, const float* bB,
                                              const float* __restrict__ w,
                                              float* outA, float* outB) {
    ull cA[4] = {0, 0, 0, 0}, cB[4] = {0, 0, 0, 0};
#pragma unroll
    for (int i = 0; i < 8; ++i) {
        ull tA[4] = {0, 0, 0, 0}, tB[4] = {0, 0, 0, 0};
        const float* base = w + i * 64;
#pragma unroll
        for (int j = 0; j < 8; ++j) {
            const ulonglong2* wp = reinterpret_cast<const ulonglong2*>(base + j * 8);
            ulonglong2 W01 = wp[0];
            ulonglong2 W23 = wp[1];
            ull bb = bcast2(bA[j]);
            tA[0] = ffma2(bb, W01.x, tA[0]);  tA[1] = ffma2(bb, W01.y, tA[1]);
            tA[2] = ffma2(bb, W23.x, tA[2]);  tA[3] = ffma2(bb, W23.y, tA[3]);
            bb = bcast2(bB[j]);
            tB[0] = ffma2(bb, W01.x, tB[0]);  tB[1] = ffma2(bb, W01.y, tB[1]);
            tB[2] = ffma2(bb, W23.x, tB[2]);  tB[3] = ffma2(bb, W23.y, tB[3]);
        }
        ull ai = bcast2(aA[i]);
        cA[0] = ffma2(ai, tA[0], cA[0]);  cA[1] = ffma2(ai, tA[1], cA[1]);
        cA[2] = ffma2(ai, tA[2], cA[2]);  cA[3] = ffma2(ai, tA[3], cA[3]);
        ai = bcast2(aB[i]);
        cB[0] = ffma2(ai, tB[0], cB[0]);  cB[1] = ffma2(ai, tB[1], cB[1]);
        cB[2] = ffma2(ai, tB[2], cB[2]);  cB[3] = ffma2(ai, tB[3], cB[3]);
    }
    unpack2(cA[0], outA[0], outA[1]);  unpack2(cA[1], outA[2], outA[3]);
    unpack2(cA[2], outA[4], outA[5]);  unpack2(cA[3], outA[6], outA[7]);
    unpack2(cB[0], outB[0], outB[1]);  unpack2(cB[1], outB[2], outB[3]);
    unpack2(cB[2], outB[4], outB[5]);  unpack2(cB[3], outB[6], outB[7]);
}

__device__ __forceinline__ void scopy4(float* dst, const float* __restrict__ src, int n4) {
    const float4* s = reinterpret_cast<const float4*>(src);
    float4* d = reinterpret_cast<float4*>(dst);
    for (int i = threadIdx.x; i < n4; i += blockDim.x) d[i] = s[i];
}

__device__ __forceinline__ void store_pair(float4* buf, int b, const float* v) {
    buf[(size_t)b * 2 + 0] = make_float4(v[0], v[1], v[2], v[3]);
    buf[(size_t)b * 2 + 1] = make_float4(v[4], v[5], v[6], v[7]);
}
__device__ __forceinline__ void load_pair(const float4* buf, int b, float* v) {
    float4 p0 = buf[(size_t)b * 2 + 0];
    float4 p1 = buf[(size_t)b * 2 + 1];
    v[0] = p0.x; v[1] = p0.y; v[2] = p0.z; v[3] = p0.w;
    v[4] = p1.x; v[5] = p1.y; v[6] = p1.z; v[7] = p1.w;
}

__global__ void __launch_bounds__(T1, 5)
tn_eighth_kernel(const float* __restrict__ x,
                 const float* __restrict__ w7, const float* __restrict__ w6,
                 const float* __restrict__ w5, const float* __restrict__ w4,
                 const float* __restrict__ w3) {
    extern __shared__ float sw[];

    const int e   = blockIdx.x >> 8;      // eighth 0..7
    const int blk = blockIdx.x & 255;

    // stage this eighth's weights
    scopy4(sw + E7, w7 + e * 256,   256 / 4);
    scopy4(sw + E6, w6 + e * 1024, 1024 / 4);
    scopy4(sw + E5, w5 + e * 2048, 2048 / 4);
    scopy4(sw + E4, w4 + e * 1024, 1024 / 4);
    scopy4(sw + E3, w3 + e * 512,   512 / 4);
    __syncthreads();

    const int bA = blk * T1 + threadIdx.x;     // sample A
    const int bB = bA + HALF;                  // sample B
    const float4* xA = reinterpret_cast<const float4*>(x) + (size_t)bA * 128 + e * 16;
    const float4* xB = reinterpret_cast<const float4*>(x) + (size_t)bB * 128 + e * 16;

    float stkA0[8], stkA1[8], stkA2[8];
    float stkB0[8], stkB1[8], stkB2[8];

#pragma unroll 1
    for (int m = 0; m < 8; ++m) {
        float4 qA0 = __ldg(xA + 2 * m);
        float4 qA1 = __ldg(xA + 2 * m + 1);
        float4 qB0 = __ldg(xB + 2 * m);
        float4 qB1 = __ldg(xB + 2 * m + 1);

        float laA[4], lbA[4], laB[4], lbB[4];
        leaf2(qA0, qB0, sw + E7 + (2 * m) * 16, laA, laB);
        leaf2(qA1, qB1, sw + E7 + (2 * m + 1) * 16, lbA, lbB);

        float curA[8], curB[8];
        contract448_2(laA, lbA, laB, lbB, sw + E6 + m * 128, curA, curB);

        if (!(m & 1)) {
            cp8(stkA0, curA);  cp8(stkB0, curB);
        } else {
            contract888_2(stkA0, curA, stkB0, curB, sw + E5 + (m >> 1) * 512, curA, curB);
            if (!((m >> 1) & 1)) {
                cp8(stkA1, curA);  cp8(stkB1, curB);
            } else {
                contract888_2(stkA1, curA, stkB1, curB, sw + E4 + (m >> 2) * 512, curA, curB);
                if (!((m >> 2) & 1)) {
                    cp8(stkA2, curA);  cp8(stkB2, curB);
                } else {
                    // m == 7: top of this eighth (w3 node)
                    contract888_2(stkA2, curA, stkB2, curB, sw + E3, curA, curB);
                    float4* eb = g_ebuf + ((size_t)e * NB) * 2;
                    store_pair(eb, bA, curA);
                    store_pair(eb, bB, curB);
                }
            }
        }
    }
}

// merge: w2 (4 nodes), w1 (2 nodes), w0 root; 2 samples/thread.
__global__ void __launch_bounds__(T2)
tn_merge_kernel(const float* __restrict__ w2, const float* __restrict__ w1,
                const float* __restrict__ w0, float* __restrict__ out) {
    __shared__ float w2s[2048];
    __shared__ float w1s[1024];
    __shared__ float w0s[128];
    scopy4(w2s, w2, 2048 / 4);
    scopy4(w1s, w1, 1024 / 4);
    scopy4(w0s, w0, 128 / 4);
    __syncthreads();

    const int bA = blockIdx.x * T2 + threadIdx.x;
    const int bB = bA + HALF;

    float hLA[8], hLB[8], hRA[8], hRB[8];

    // left half: eighths 0..3 -> w2 nodes 0,1 -> w1 node 0
    {
        float vA0[8], vA1[8], vB0[8], vB1[8];
        load_pair(g_ebuf + 0 * (size_t)NB * 2, bA, vA0);
        load_pair(g_ebuf + 1 * (size_t)NB * 2, bA, vA1);
        load_pair(g_ebuf + 0 * (size_t)NB * 2, bB, vB0);
        load_pair(g_ebuf + 1 * (size_t)NB * 2, bB, vB1);
        float pA0[8], pB0[8];
        contract888_2(vA0, vA1, vB0, vB1, w2s, pA0, pB0);

        load_pair(g_ebuf + 2 * (size_t)NB * 2, bA, vA0);
        load_pair(g_ebuf + 3 * (size_t)NB * 2, bA, vA1);
        load_pair(g_ebuf + 2 * (size_t)NB * 2, bB, vB0);
        load_pair(g_ebuf + 3 * (size_t)NB * 2, bB, vB1);
        float pA1[8], pB1[8];
        contract888_2(vA0, vA1, vB0, vB1, w2s + 512, pA1, pB1);

        contract888_2(pA0, pA1, pB0, pB1, w1s, hLA, hLB);
    }
    // right half: eighths 4..7 -> w2 nodes 2,3 -> w1 node 1
    {
        float vA0[8], vA1[8], vB0[8], vB1[8];
        load_pair(g_ebuf + 4 * (size_t)NB * 2, bA, vA0);
        load_pair(g_ebuf + 5 * (size_t)NB * 2, bA, vA1);
        load_pair(g_ebuf + 4 * (size_t)NB * 2, bB, vB0);
        load_pair(g_ebuf + 5 * (size_t)NB * 2, bB, vB1);
        float pA0[8], pB0[8];
        contract888_2(vA0, vA1, vB0, vB1, w2s + 1024, pA0, pB0);

        load_pair(g_ebuf + 6 * (size_t)NB * 2, bA, vA0);
        load_pair(g_ebuf + 7 * (size_t)NB * 2, bA, vA1);
        load_pair(g_ebuf + 6 * (size_t)NB * 2, bB, vB0);
        load_pair(g_ebuf + 7 * (size_t)NB * 2, bB, vB1);
        float pA1[8], pB1[8];
        contract888_2(vA0, vA1, vB0, vB1, w2s + 1536, pA1, pB1);

        contract888_2(pA0, pA1, pB0, pB1, w1s + 512, hRA, hRB);
    }

    // root for both samples
    ull accA = 0ull, accB = 0ull;
#pragma unroll
    for (int i = 0; i < 8; ++i) {
        ull aiA = bcast2(hLA[i]);
        ull aiB = bcast2(hLB[i]);
#pragma unroll
        for (int j = 0; j < 8; ++j) {
            ull W = *reinterpret_cast<const ull*>(w0s + (i * 8 + j) * 2);
            accA = ffma2(ffma2(aiA, bcast2(hRA[j]), 0ull), W, accA);
            accB = ffma2(ffma2(aiB, bcast2(hRB[j]), 0ull), W, accB);
        }
    }
    float r0, r1;
    unpack2(accA, r0, r1);
    reinterpret_cast<float2*>(out)[bA] = make_float2(r0, r1);
    unpack2(accB, r0, r1);
    reinterpret_cast<float2*>(out)[bB] = make_float2(r0, r1);
}

extern "C" void kernel_launch(void* const* d_in, const int* in_sizes, int n_in,
                              void* d_out, int out_size) {
    const float* x  = (const float*)d_in[0];
    const float* w7 = (const float*)d_in[1];
    const float* w6 = (const float*)d_in[2];
    const float* w5 = (const float*)d_in[3];
    const float* w4 = (const float*)d_in[4];
    const float* w3 = (const float*)d_in[5];
    const float* w2 = (const float*)d_in[6];
    const float* w1 = (const float*)d_in[7];
    const float* w0 = (const float*)d_in[8];
    float* out = (float*)d_out;

    const size_t smem = SMEM1_FLOATS * sizeof(float);
    cudaFuncSetAttribute(tn_eighth_kernel, cudaFuncAttributeMaxDynamicSharedMemorySize, (int)smem);
    tn_eighth_kernel<<<NBLOCKS1, T1, smem>>>(x, w7, w6, w5, w4, w3);
    tn_merge_kernel<<<NBLOCKS2, T2>>>(w2, w1, w0, out);
}

// round 6
// speedup vs baseline: 1.0685x; 1.0685x over previous
#include <cuda_runtime.h>

// ---------------------------------------------------------------------------
// TNModel binary-tree TN, B=65536. Round 6: eighth-split @ 4 CTAs/SM
// (128-reg cap with ~10 regs headroom), manual weight-prefetch software
// pipeline in the 8x8x8 contraction, merge kernel at 1 sample/thread.
// ---------------------------------------------------------------------------

#define NB       65536
#define HALF     (NB / 2)            // 32768
#define T1       128                 // threads, kernel 1
#define BLK_E    (HALF / T1)         // 256 blocks per eighth
#define NBLOCKS1 (8 * BLK_E)         // 2048
#define T2       256                 // threads, kernel 2
#define NBLOCKS2 (NB / T2)           // 256 (1 sample/thread)

// eighth-tree shared-memory float offsets
#define E7 0                      // 16 x 16   =  256
#define E6 (E7 + 256)             //  8 x 128  = 1024
#define E5 (E6 + 1024)            //  4 x 512  = 2048
#define E4 (E5 + 2048)            //  2 x 512  = 1024
#define E3 (E4 + 1024)            //  1 x 512  =  512
#define SMEM1_FLOATS (E3 + 512)   // 4864 floats = 19456 bytes

typedef unsigned long long ull;

__device__ float4 g_ebuf[8 * NB * 2];   // [eighth][sample][2 x float4]

__device__ __forceinline__ ull ffma2(ull a, ull b, ull c) {
    ull d;
    asm("fma.rn.f32x2 %0, %1, %2, %3;" : "=l"(d) : "l"(a), "l"(b), "l"(c));
    return d;
}
__device__ __forceinline__ ull bcast2(float x) {
    ull r;
    asm("mov.b64 %0, {%1, %1};" : "=l"(r) : "f"(x));
    return r;
}
__device__ __forceinline__ void unpack2(ull v, float& lo, float& hi) {
    asm("mov.b64 {%0, %1}, %2;" : "=f"(lo), "=f"(hi) : "l"(v));
}
__device__ __forceinline__ void cp8(float* d, const float* s) {
#pragma unroll
    for (int k = 0; k < 8; ++k) d[k] = s[k];
}

// leaf for two samples sharing W (16 floats)
__device__ __forceinline__ void leaf2(float4 qa, float4 qb,
                                      const float* __restrict__ w,
                                      float* hA, float* hB) {
    ull cA0 = 0, cA1 = 0, cB0 = 0, cB1 = 0;
    float eA[2] = {qa.x, qa.y}, oA[2] = {qa.z, qa.w};
    float eB[2] = {qb.x, qb.y}, oB[2] = {qb.z, qb.w};
#pragma unroll
    for (int i = 0; i < 2; ++i) {
#pragma unroll
        for (int j = 0; j < 2; ++j) {
            const ulonglong2 W = *reinterpret_cast<const ulonglong2*>(w + (i * 2 + j) * 4);
            ull pA = bcast2(eA[i] * oA[j]);
            ull pB = bcast2(eB[i] * oB[j]);
            cA0 = ffma2(pA, W.x, cA0);  cA1 = ffma2(pA, W.y, cA1);
            cB0 = ffma2(pB, W.x, cB0);  cB1 = ffma2(pB, W.y, cB1);
        }
    }
    unpack2(cA0, hA[0], hA[1]);  unpack2(cA1, hA[2], hA[3]);
    unpack2(cB0, hB[0], hB[1]);  unpack2(cB1, hB[2], hB[3]);
}

// 4x4->8, two samples sharing W (128 floats)
__device__ __forceinline__ void contract448_2(const float* aA, const float* bA,
                                              const float* aB, const float* bB,
                                              const float* __restrict__ w,
                                              float* outA, float* outB) {
    ull cA[4] = {0, 0, 0, 0}, cB[4] = {0, 0, 0, 0};
#pragma unroll
    for (int i = 0; i < 4; ++i) {
        ull tA[4] = {0, 0, 0, 0}, tB[4] = {0, 0, 0, 0};
#pragma unroll
        for (int j = 0; j < 4; ++j) {
            const ulonglong2* wp = reinterpret_cast<const ulonglong2*>(w + (i * 4 + j) * 8);
            ulonglong2 W01 = wp[0];
            ulonglong2 W23 = wp[1];
            ull bb = bcast2(bA[j]);
            tA[0] = ffma2(bb, W01.x, tA[0]);  tA[1] = ffma2(bb, W01.y, tA[1]);
            tA[2] = ffma2(bb, W23.x, tA[2]);  tA[3] = ffma2(bb, W23.y, tA[3]);
            bb = bcast2(bB[j]);
            tB[0] = ffma2(bb, W01.x, tB[0]);  tB[1] = ffma2(bb, W01.y, tB[1]);
            tB[2] = ffma2(bb, W23.x, tB[2]);  tB[3] = ffma2(bb, W23.y, tB[3]);
        }
        ull ai = bcast2(aA[i]);
        cA[0] = ffma2(ai, tA[0], cA[0]);  cA[1] = ffma2(ai, tA[1], cA[1]);
        cA[2] = ffma2(ai, tA[2], cA[2]);  cA[3] = ffma2(ai, tA[3], cA[3]);
        ai = bcast2(aB[i]);
        cB[0] = ffma2(ai, tB[0], cB[0]);  cB[1] = ffma2(ai, tB[1], cB[1]);
        cB[2] = ffma2(ai, tB[2], cB[2]);  cB[3] = ffma2(ai, tB[3], cB[3]);
    }
    unpack2(cA[0], outA[0], outA[1]);  unpack2(cA[1], outA[2], outA[3]);
    unpack2(cA[2], outA[4], outA[5]);  unpack2(cA[3], outA[6], outA[7]);
    unpack2(cB[0], outB[0], outB[1]);  unpack2(cB[1], outB[2], outB[3]);
    unpack2(cB[2], outB[4], outB[5]);  unpack2(cB[3], outB[6], outB[7]);
}

// 8x8->8, two samples sharing W (512 floats), software-pipelined weight loads.
// out may alias b.
__device__ __forceinline__ void contract888_2(const float* aA, const float* bA,
                                              const float* aB, const float* bB,
                                              const float* __restrict__ w,
                                              float* outA, float* outB) {
    const ulonglong2* wp = reinterpret_cast<const ulonglong2*>(w);
    ull cA[4] = {0, 0, 0, 0}, cB[4] = {0, 0, 0, 0};
    ulonglong2 W01 = wp[0];
    ulonglong2 W23 = wp[1];
#pragma unroll
    for (int i = 0; i < 8; ++i) {
        ull tA[4] = {0, 0, 0, 0}, tB[4] = {0, 0, 0, 0};
#pragma unroll
        for (int j = 0; j < 8; ++j) {
            // prefetch next weight pair (one j-iteration of load-use distance)
            const int nidx = i * 8 + j + 1;
            ulonglong2 nW01, nW23;
            if (nidx < 64) {
                nW01 = wp[2 * nidx];
                nW23 = wp[2 * nidx + 1];
            }
            ull bb = bcast2(bA[j]);
            tA[0] = ffma2(bb, W01.x, tA[0]);  tA[1] = ffma2(bb, W01.y, tA[1]);
            tA[2] = ffma2(bb, W23.x, tA[2]);  tA[3] = ffma2(bb, W23.y, tA[3]);
            bb = bcast2(bB[j]);
            tB[0] = ffma2(bb, W01.x, tB[0]);  tB[1] = ffma2(bb, W01.y, tB[1]);
            tB[2] = ffma2(bb, W23.x, tB[2]);  tB[3] = ffma2(bb, W23.y, tB[3]);
            if (nidx < 64) { W01 = nW01; W23 = nW23; }
        }
        ull ai = bcast2(aA[i]);
        cA[0] = ffma2(ai, tA[0], cA[0]);  cA[1] = ffma2(ai, tA[1], cA[1]);
        cA[2] = ffma2(ai, tA[2], cA[2]);  cA[3] = ffma2(ai, tA[3], cA[3]);
        ai = bcast2(aB[i]);
        cB[0] = ffma2(ai, tB[0], cB[0]);  cB[1] = ffma2(ai, tB[1], cB[1]);
        cB[2] = ffma2(ai, tB[2], cB[2]);  cB[3] = ffma2(ai, tB[3], cB[3]);
    }
    unpack2(cA[0], outA[0], outA[1]);  unpack2(cA[1], outA[2], outA[3]);
    unpack2(cA[2], outA[4], outA[5]);  unpack2(cA[3], outA[6], outA[7]);
    unpack2(cB[0], outB[0], outB[1]);  unpack2(cB[1], outB[2], outB[3]);
    unpack2(cB[2], outB[4], outB[5]);  unpack2(cB[3], outB[6], outB[7]);
}

// 8x8->8 single sample (merge kernel)
__device__ __forceinline__ void contract888_1(const float* a, const float* b,
                                              const float* __restrict__ w, float* out) {
    ull c[4] = {0, 0, 0, 0};
#pragma unroll
    for (int i = 0; i < 8; ++i) {
        ull t[4] = {0, 0, 0, 0};
        const float* base = w + i * 64;
#pragma unroll
        for (int j = 0; j < 8; ++j) {
            const ulonglong2* wp = reinterpret_cast<const ulonglong2*>(base + j * 8);
            ulonglong2 W01 = wp[0];
            ulonglong2 W23 = wp[1];
            ull bb = bcast2(b[j]);
            t[0] = ffma2(bb, W01.x, t[0]);  t[1] = ffma2(bb, W01.y, t[1]);
            t[2] = ffma2(bb, W23.x, t[2]);  t[3] = ffma2(bb, W23.y, t[3]);
        }
        ull ai = bcast2(a[i]);
        c[0] = ffma2(ai, t[0], c[0]);  c[1] = ffma2(ai, t[1], c[1]);
        c[2] = ffma2(ai, t[2], c[2]);  c[3] = ffma2(ai, t[3], c[3]);
    }
    unpack2(c[0], out[0], out[1]);  unpack2(c[1], out[2], out[3]);
    unpack2(c[2], out[4], out[5]);  unpack2(c[3], out[6], out[7]);
}

__device__ __forceinline__ void scopy4(float* dst, const float* __restrict__ src, int n4) {
    const float4* s = reinterpret_cast<const float4*>(src);
    float4* d = reinterpret_cast<float4*>(dst);
    for (int i = threadIdx.x; i < n4; i += blockDim.x) d[i] = s[i];
}

__device__ __forceinline__ void store_pair(float4* buf, int b, const float* v) {
    buf[(size_t)b * 2 + 0] = make_float4(v[0], v[1], v[2], v[3]);
    buf[(size_t)b * 2 + 1] = make_float4(v[4], v[5], v[6], v[7]);
}
__device__ __forceinline__ void load_pair(const float4* buf, int b, float* v) {
    float4 p0 = buf[(size_t)b * 2 + 0];
    float4 p1 = buf[(size_t)b * 2 + 1];
    v[0] = p0.x; v[1] = p0.y; v[2] = p0.z; v[3] = p0.w;
    v[4] = p1.x; v[5] = p1.y; v[6] = p1.z; v[7] = p1.w;
}

__global__ void __launch_bounds__(T1, 4)
tn_eighth_kernel(const float* __restrict__ x,
                 const float* __restrict__ w7, const float* __restrict__ w6,
                 const float* __restrict__ w5, const float* __restrict__ w4,
                 const float* __restrict__ w3) {
    extern __shared__ float sw[];

    const int e   = blockIdx.x >> 8;      // eighth 0..7
    const int blk = blockIdx.x & 255;

    scopy4(sw + E7, w7 + e * 256,   256 / 4);
    scopy4(sw + E6, w6 + e * 1024, 1024 / 4);
    scopy4(sw + E5, w5 + e * 2048, 2048 / 4);
    scopy4(sw + E4, w4 + e * 1024, 1024 / 4);
    scopy4(sw + E3, w3 + e * 512,   512 / 4);
    __syncthreads();

    const int bA = blk * T1 + threadIdx.x;
    const int bB = bA + HALF;
    const float4* xA = reinterpret_cast<const float4*>(x) + (size_t)bA * 128 + e * 16;
    const float4* xB = reinterpret_cast<const float4*>(x) + (size_t)bB * 128 + e * 16;

    float stkA0[8], stkA1[8], stkA2[8];
    float stkB0[8], stkB1[8], stkB2[8];

#pragma unroll 1
    for (int m = 0; m < 8; ++m) {
        float4 qA0 = __ldg(xA + 2 * m);
        float4 qA1 = __ldg(xA + 2 * m + 1);
        float4 qB0 = __ldg(xB + 2 * m);
        float4 qB1 = __ldg(xB + 2 * m + 1);

        float laA[4], lbA[4], laB[4], lbB[4];
        leaf2(qA0, qB0, sw + E7 + (2 * m) * 16, laA, laB);
        leaf2(qA1, qB1, sw + E7 + (2 * m + 1) * 16, lbA, lbB);

        float curA[8], curB[8];
        contract448_2(laA, lbA, laB, lbB, sw + E6 + m * 128, curA, curB);

        if (!(m & 1)) {
            cp8(stkA0, curA);  cp8(stkB0, curB);
        } else {
            contract888_2(stkA0, curA, stkB0, curB, sw + E5 + (m >> 1) * 512, curA, curB);
            if (!((m >> 1) & 1)) {
                cp8(stkA1, curA);  cp8(stkB1, curB);
            } else {
                contract888_2(stkA1, curA, stkB1, curB, sw + E4 + (m >> 2) * 512, curA, curB);
                if (!((m >> 2) & 1)) {
                    cp8(stkA2, curA);  cp8(stkB2, curB);
                } else {
                    // m == 7: top of this eighth (w3 node)
                    contract888_2(stkA2, curA, stkB2, curB, sw + E3, curA, curB);
                    float4* eb = g_ebuf + ((size_t)e * NB) * 2;
                    store_pair(eb, bA, curA);
                    store_pair(eb, bB, curB);
                }
            }
        }
    }
}

// merge: w2 (4 nodes), w1 (2 nodes), w0 root; 1 sample/thread for occupancy.
__global__ void __launch_bounds__(T2)
tn_merge_kernel(const float* __restrict__ w2, const float* __restrict__ w1,
                const float* __restrict__ w0, float* __restrict__ out) {
    __shared__ float w2s[2048];
    __shared__ float w1s[1024];
    __shared__ float w0s[128];
    scopy4(w2s, w2, 2048 / 4);
    scopy4(w1s, w1, 1024 / 4);
    scopy4(w0s, w0, 128 / 4);
    __syncthreads();

    const int b = blockIdx.x * T2 + threadIdx.x;

    float v0[8], v1[8], hL[8], hR[8], p0[8], p1[8];

    // left half: eighths 0..3 -> w2 nodes 0,1 -> w1 node 0
    load_pair(g_ebuf + 0 * (size_t)NB * 2, b, v0);
    load_pair(g_ebuf + 1 * (size_t)NB * 2, b, v1);
    contract888_1(v0, v1, w2s, p0);
    load_pair(g_ebuf + 2 * (size_t)NB * 2, b, v0);
    load_pair(g_ebuf + 3 * (size_t)NB * 2, b, v1);
    contract888_1(v0, v1, w2s + 512, p1);
    contract888_1(p0, p1, w1s, hL);

    // right half: eighths 4..7 -> w2 nodes 2,3 -> w1 node 1
    load_pair(g_ebuf + 4 * (size_t)NB * 2, b, v0);
    load_pair(g_ebuf + 5 * (size_t)NB * 2, b, v1);
    contract888_1(v0, v1, w2s + 1024, p0);
    load_pair(g_ebuf + 6 * (size_t)NB * 2, b, v0);
    load_pair(g_ebuf + 7 * (size_t)NB * 2, b, v1);
    contract888_1(v0, v1, w2s + 1536, p1);
    contract888_1(p0, p1, w1s + 512, hR);

    ull acc = 0ull;
#pragma unroll
    for (int i = 0; i < 8; ++i) {
        ull ai = bcast2(hL[i]);
#pragma unroll
        for (int j = 0; j < 8; ++j) {
            ull W = *reinterpret_cast<const ull*>(w0s + (i * 8 + j) * 2);
            acc = ffma2(ffma2(ai, bcast2(hR[j]), 0ull), W, acc);
        }
    }
    float r0, r1;
    unpack2(acc, r0, r1);
    reinterpret_cast<float2*>(out)[b] = make_float2(r0, r1);
}

extern "C" void kernel_launch(void* const* d_in, const int* in_sizes, int n_in,
                              void* d_out, int out_size) {
    const float* x  = (const float*)d_in[0];
    const float* w7 = (const float*)d_in[1];
    const float* w6 = (const float*)d_in[2];
    const float* w5 = (const float*)d_in[3];
    const float* w4 = (const float*)d_in[4];
    const float* w3 = (const float*)d_in[5];
    const float* w2 = (const float*)d_in[6];
    const float* w1 = (const float*)d_in[7];
    const float* w0 = (const float*)d_in[8];
    float* out = (float*)d_out;

    const size_t smem = SMEM1_FLOATS * sizeof(float);
    cudaFuncSetAttribute(tn_eighth_kernel, cudaFuncAttributeMaxDynamicSharedMemorySize, (int)smem);
    tn_eighth_kernel<<<NBLOCKS1, T1, smem>>>(x, w7, w6, w5, w4, w3);
    tn_merge_kernel<<<NBLOCKS2, T2>>>(w2, w1, w0, out);
}